// round 4
// baseline (speedup 1.0000x reference)
#include <cuda_runtime.h>
#include <cstdint>

// Problem constants
#define BB   8
#define CIN  64
#define COUT 64
#define RN   4
#define HH   128
#define WW   128

// Tiling
#define TH   4            // output rows per block
#define TW   32           // output cols per block
#define XROWS 6           // TH + 2 halo
#define XP   35           // x smem pitch (bank-conflict-free for our lane map)
#define WPITCH 66         // W smem pitch (even -> aligned LDS.64, 2-way STS worst case)
#define ICB  8            // ic chunk per W stage
#define NTHR 256

#define SX_FLOATS (CIN*XROWS*XP)   // 13440
#define SW_FLOATS (ICB*9*WPITCH)   // 4752
#define SM_FLOATS (RN*TH*TW)       // 512
#define SMEM_BYTES ((SX_FLOATS + SW_FLOATS + SM_FLOATS) * 4)

#define MASK_BASE ((size_t)BB*COUT*HH*WW)   // 8388608

typedef unsigned long long u64;

__device__ __forceinline__ u64 pk2(float a, float b) {
    u64 r; asm("mov.b64 %0, {%1, %2};" : "=l"(r) : "f"(a), "f"(b)); return r;
}
__device__ __forceinline__ void up2(u64 v, float& a, float& b) {
    asm("mov.b64 {%0, %1}, %2;" : "=f"(a), "=f"(b) : "l"(v));
}
// packed dual-fp32 FMA (FFMA2): d = a*b + c lanewise
__device__ __forceinline__ u64 f2ma(u64 a, u64 b, u64 c) {
    u64 d; asm("fma.rn.f32x2 %0, %1, %2, %3;" : "=l"(d) : "l"(a), "l"(b), "l"(c)); return d;
}

extern "C" __global__ void __launch_bounds__(NTHR, 2)
hrc_kernel(const float* __restrict__ x,     const float* __restrict__ kern,
           const float* __restrict__ maskw, const float* __restrict__ maskb,
           const float* __restrict__ bn_g,  const float* __restrict__ bn_b,
           const float* __restrict__ bn_m,  const float* __restrict__ bn_v,
           float* __restrict__ out)
{
    extern __shared__ float smem[];
    float* sx = smem;                 // [CIN][XROWS][XP]
    float* sw = smem + SX_FLOATS;     // W chunk [i*9+t][WPITCH] (oc in row) / mask_w overlay
    float* sm = sw + SW_FLOATS;       // masks [RN][TH*TW]

    const int b   = blockIdx.z;
    const int h0  = blockIdx.y * TH;
    const int w0  = blockIdx.x * TW;
    const int tid = threadIdx.x;

    // ---------------- load x tile (64 ch + halo), SAME zero-padding ----------------
    const float* xb = x + (size_t)b * CIN * HH * WW;
    for (int idx = tid; idx < CIN * XROWS * (TW + 2); idx += NTHR) {
        int ic  = idx / (XROWS * (TW + 2));
        int rem = idx - ic * (XROWS * (TW + 2));
        int r   = rem / (TW + 2);
        int c   = rem - r * (TW + 2);
        int gh = h0 - 1 + r, gw = w0 - 1 + c;
        float v = 0.f;
        if ((unsigned)gh < HH && (unsigned)gw < WW)
            v = xb[(ic * HH + gh) * WW + gw];
        sx[(ic * XROWS + r) * XP + c] = v;
    }
    // mask_w (2304 floats) overlaid into sw
    for (int idx = tid; idx < RN * CIN * 9; idx += NTHR) sw[idx] = maskw[idx];
    __syncthreads();

    // ---------------- phase 1: region logits -> softmax masks ----------------
    // 256 threads: 128 px, split ic range in two halves; combine via smem partials.
    {
        float* spart = sw + RN * CIN * 9;   // 512 floats scratch (fits in sw: 2304+512<=4752)
        const int px   = tid & 127;
        const int half = tid >> 7;
        const int row = px >> 5, col = px & 31;
        float lg[RN] = {0.f, 0.f, 0.f, 0.f};
        const int ic_lo = half * (CIN / 2), ic_hi = ic_lo + CIN / 2;
        for (int ic = ic_lo; ic < ic_hi; ic++) {
            const float* xp = &sx[(ic * XROWS + row) * XP + col];
            float xv[9];
            #pragma unroll
            for (int kh = 0; kh < 3; kh++)
                #pragma unroll
                for (int kw = 0; kw < 3; kw++) xv[kh * 3 + kw] = xp[kh * XP + kw];
            #pragma unroll
            for (int r = 0; r < RN; r++) {
                const float* wp = &sw[(r * CIN + ic) * 9];
                #pragma unroll
                for (int t = 0; t < 9; t++) lg[r] = fmaf(wp[t], xv[t], lg[r]);
            }
        }
        if (half == 1) {
            #pragma unroll
            for (int r = 0; r < RN; r++) spart[r * 128 + px] = lg[r];
        }
        __syncthreads();
        if (half == 0) {
            #pragma unroll
            for (int r = 0; r < RN; r++) lg[r] += spart[r * 128 + px] + maskb[r];
            float mx = fmaxf(fmaxf(lg[0], lg[1]), fmaxf(lg[2], lg[3]));
            float e[RN]; float s = 0.f;
            #pragma unroll
            for (int r = 0; r < RN; r++) { e[r] = expf(lg[r] - mx); s += e[r]; }
            float inv = 1.f / s;
            #pragma unroll
            for (int r = 0; r < RN; r++) {
                float m = e[r] * inv;
                sm[r * (TH * TW) + px] = m;
                out[MASK_BASE + ((size_t)(b * RN + r) * HH + (h0 + row)) * WW + (w0 + col)] = m;
            }
        }
        __syncthreads();
    }

    // ---------------- phase 2: dynamic conv, region-folded ----------------
    // Thread computes 8 oc (as 4 f32x2 pairs) x 4 px (along w).
    const int ocg8 = (tid >> 5) << 3;        // warp-uniform -> broadcast W reads
    const int pxg  = tid & 31;
    const int prow = pxg >> 3;               // 0..3
    const int pcol = (pxg & 7) << 2;         // 0,4,...,28

    u64 accF[4][4];
    const u64 Z = pk2(0.f, 0.f);
    #pragma unroll
    for (int j = 0; j < 4; j++)
        #pragma unroll
        for (int p = 0; p < 4; p++) accF[j][p] = Z;

    for (int r = 0; r < RN; r++) {
        u64 accR[4][4];
        #pragma unroll
        for (int j = 0; j < 4; j++)
            #pragma unroll
            for (int p = 0; p < 4; p++) accR[j][p] = Z;

        for (int ic0 = 0; ic0 < CIN; ic0 += ICB) {
            __syncthreads();
            // stage W chunk: [oc][ic0..ic0+7][9] -> sw[(i*9+t)*WPITCH + oc]
            const float* kc = kern + (size_t)(b * RN + r) * (COUT * CIN * 9) + ic0 * 9;
            #pragma unroll 1
            for (int s = tid; s < COUT * ICB * 9; s += NTHR) {
                int oc  = s / (ICB * 9);
                int rem = s - oc * (ICB * 9);          // = i*9 + t
                sw[rem * WPITCH + oc] = kc[oc * (CIN * 9) + rem];
            }
            __syncthreads();

            #pragma unroll 2
            for (int i = 0; i < ICB; i++) {
                #pragma unroll
                for (int kh = 0; kh < 3; kh++) {
                    const float* xp = &sx[((ic0 + i) * XROWS + prow + kh) * XP + pcol];
                    u64 xx[6];
                    #pragma unroll
                    for (int q = 0; q < 6; q++) { float xv = xp[q]; xx[q] = pk2(xv, xv); }
                    #pragma unroll
                    for (int kw = 0; kw < 3; kw++) {
                        const float* wp = &sw[(i * 9 + kh * 3 + kw) * WPITCH + ocg8];
                        u64 w01 = *(const u64*)(wp);
                        u64 w23 = *(const u64*)(wp + 2);
                        u64 w45 = *(const u64*)(wp + 4);
                        u64 w67 = *(const u64*)(wp + 6);
                        #pragma unroll
                        for (int p = 0; p < 4; p++) {
                            u64 xv2 = xx[kw + p];
                            accR[0][p] = f2ma(w01, xv2, accR[0][p]);
                            accR[1][p] = f2ma(w23, xv2, accR[1][p]);
                            accR[2][p] = f2ma(w45, xv2, accR[2][p]);
                            accR[3][p] = f2ma(w67, xv2, accR[3][p]);
                        }
                    }
                }
            }
        }
        // fold this region with its mask weight
        #pragma unroll
        for (int p = 0; p < 4; p++) {
            float m = sm[r * (TH * TW) + prow * TW + pcol + p];
            u64 mm = pk2(m, m);
            #pragma unroll
            for (int j = 0; j < 4; j++) accF[j][p] = f2ma(mm, accR[j][p], accF[j][p]);
        }
    }

    // ---------------- epilogue: BN (eval) + ReLU, float4 stores ----------------
    const size_t obase = (size_t)b * COUT * HH * WW;
    const int gh = h0 + prow;
    const int gwc = w0 + pcol;
    #pragma unroll
    for (int j = 0; j < 4; j++) {
        int oc0 = ocg8 + 2 * j;
        float i0 = bn_g[oc0]     / sqrtf(bn_v[oc0]     + 1e-5f);
        float i1 = bn_g[oc0 + 1] / sqrtf(bn_v[oc0 + 1] + 1e-5f);
        float m0 = bn_m[oc0], m1 = bn_m[oc0 + 1];
        float c0 = bn_b[oc0], c1 = bn_b[oc0 + 1];
        float v0[4], v1[4];
        #pragma unroll
        for (int p = 0; p < 4; p++) {
            float a0, a1; up2(accF[j][p], a0, a1);
            v0[p] = fmaxf((a0 - m0) * i0 + c0, 0.f);
            v1[p] = fmaxf((a1 - m1) * i1 + c1, 0.f);
        }
        *(float4*)&out[obase + ((size_t)oc0 * HH + gh) * WW + gwc] =
            make_float4(v0[0], v0[1], v0[2], v0[3]);
        *(float4*)&out[obase + ((size_t)(oc0 + 1) * HH + gh) * WW + gwc] =
            make_float4(v1[0], v1[1], v1[2], v1[3]);
    }
}

extern "C" void kernel_launch(void* const* d_in, const int* in_sizes, int n_in,
                              void* d_out, int out_size)
{
    const float* x  = (const float*)d_in[0];
    const float* k  = (const float*)d_in[1];
    const float* mw = (const float*)d_in[2];
    const float* mb = (const float*)d_in[3];
    const float* g  = (const float*)d_in[4];
    const float* be = (const float*)d_in[5];
    const float* mn = (const float*)d_in[6];
    const float* vr = (const float*)d_in[7];

    cudaFuncSetAttribute(hrc_kernel, cudaFuncAttributeMaxDynamicSharedMemorySize, SMEM_BYTES);

    dim3 grid(WW / TW, HH / TH, BB);   // 4 x 32 x 8 = 1024 blocks
    hrc_kernel<<<grid, NTHR, SMEM_BYTES>>>(x, k, mw, mb, g, be, mn, vr, (float*)d_out);
}

// round 8
// speedup vs baseline: 2.2870x; 2.2870x over previous
#include <cuda_runtime.h>
#include <cstdint>

// Problem constants
#define BB   8
#define CIN  64
#define COUT 64
#define RN   4
#define HH   128
#define WW   128

// Tiling
#define TH   4            // output rows per block
#define TW   32           // output cols per block
#define XROWS 6           // TH + 2 halo
#define XP   36           // x smem pitch (16B-aligned rows, conflict-free LDS.128)
#define WPITCH 68         // W smem pitch (multiple of 4 -> aligned LDS.128 broadcast)
#define ICB  8            // ic chunk per W stage
#define NTHR 256
#define NSTAGE 32         // RN * (CIN/ICB)

#define SX_FLOATS (CIN*XROWS*XP)     // 13824
#define SWBUF     (ICB*9*WPITCH)     // 4896 per buffer
#define SM_FLOATS (RN*TH*TW)         // 512
#define SMEM_BYTES ((SX_FLOATS + 2*SWBUF + SM_FLOATS) * 4)   // 96512 B

#define MASK_BASE ((size_t)BB*COUT*HH*WW)   // 8388608

typedef unsigned long long u64;

__device__ __forceinline__ u64 pk2(float a, float b) {
    u64 r; asm("mov.b64 %0, {%1, %2};" : "=l"(r) : "f"(a), "f"(b)); return r;
}
__device__ __forceinline__ void up2(u64 v, float& a, float& b) {
    asm("mov.b64 {%0, %1}, %2;" : "=f"(a), "=f"(b) : "l"(v));
}
// packed dual-fp32 FMA (FFMA2): d = a*b + c lanewise
__device__ __forceinline__ u64 f2ma(u64 a, u64 b, u64 c) {
    u64 d; asm("fma.rn.f32x2 %0, %1, %2, %3;" : "=l"(d) : "l"(a), "l"(b), "l"(c)); return d;
}

__device__ __forceinline__ void cpa4(float* dst, const float* src) {
    unsigned s = (unsigned)__cvta_generic_to_shared(dst);
    asm volatile("cp.async.ca.shared.global [%0], [%1], 4;" :: "r"(s), "l"(src));
}
__device__ __forceinline__ void cpa_commit() {
    asm volatile("cp.async.commit_group;" ::: "memory");
}
__device__ __forceinline__ void cpa_wait0() {
    asm volatile("cp.async.wait_group 0;" ::: "memory");
}

// Prefetch one W stage (r = stage>>3, ic-chunk = stage&7) into buf, transposed
// to [tap(i*9+t)][oc] with pitch WPITCH. 4608 elems / 256 thr = 18 cp.async each.
__device__ __forceinline__ void prefetch_w(const float* kbase, int stage,
                                           float* buf, int tid) {
    const int rr = stage >> 3, cc = stage & 7;
    const float* kc = kbase + (size_t)rr * (COUT * CIN * 9) + cc * (ICB * 9);
    int e = tid;
    #pragma unroll
    for (int it = 0; it < 18; it++, e += NTHR) {
        int oc  = e / (ICB * 9);
        int rem = e - oc * (ICB * 9);          // i*9 + t
        cpa4(&buf[rem * WPITCH + oc], &kc[oc * (CIN * 9) + rem]);
    }
    cpa_commit();
}

extern "C" __global__ void __launch_bounds__(NTHR, 2)
hrc_kernel(const float* __restrict__ x,     const float* __restrict__ kern,
           const float* __restrict__ maskw, const float* __restrict__ maskb,
           const float* __restrict__ bn_g,  const float* __restrict__ bn_b,
           const float* __restrict__ bn_m,  const float* __restrict__ bn_v,
           float* __restrict__ out)
{
    extern __shared__ float smem[];
    float* sx  = smem;                    // [CIN][XROWS][XP]
    float* swA = smem + SX_FLOATS;        // W double buffer A (stage 0,2,...)
    float* swB = swA + SWBUF;             // W double buffer B (stage 1,3,...) / mask_w overlay
    float* sm  = swB + SWBUF;             // masks [RN][TH*TW]

    const int b   = blockIdx.z;
    const int h0  = blockIdx.y * TH;
    const int w0  = blockIdx.x * TW;
    const int tid = threadIdx.x;

    const float* kbase = kern + (size_t)b * RN * COUT * CIN * 9;

    // kick off W stage-0 prefetch immediately (lands in swA)
    prefetch_w(kbase, 0, swA, tid);

    // ---------------- load x tile (64 ch + halo), SAME zero-padding ----------------
    const float* xb = x + (size_t)b * CIN * HH * WW;
    for (int idx = tid; idx < CIN * XROWS * (TW + 2); idx += NTHR) {
        int ic  = idx / (XROWS * (TW + 2));
        int rem = idx - ic * (XROWS * (TW + 2));
        int r   = rem / (TW + 2);
        int c   = rem - r * (TW + 2);
        int gh = h0 - 1 + r, gw = w0 - 1 + c;
        float v = 0.f;
        if ((unsigned)gh < HH && (unsigned)gw < WW)
            v = xb[(ic * HH + gh) * WW + gw];
        sx[(ic * XROWS + r) * XP + c] = v;
    }
    // mask_w (2304 floats) overlaid into swB (stage-1 prefetch overwrites it later)
    for (int idx = tid; idx < RN * CIN * 9; idx += NTHR) swB[idx] = maskw[idx];
    __syncthreads();

    // ---------------- phase 1: region logits -> softmax masks ----------------
    {
        float* spart = swB + RN * CIN * 9;   // 512 floats scratch (2304+512 <= SWBUF)
        const int px   = tid & 127;
        const int half = tid >> 7;
        const int row = px >> 5, col = px & 31;
        float lg[RN] = {0.f, 0.f, 0.f, 0.f};
        const int ic_lo = half * (CIN / 2), ic_hi = ic_lo + CIN / 2;
        for (int ic = ic_lo; ic < ic_hi; ic++) {
            const float* xp = &sx[(ic * XROWS + row) * XP + col];
            float xv[9];
            #pragma unroll
            for (int kh = 0; kh < 3; kh++)
                #pragma unroll
                for (int kw = 0; kw < 3; kw++) xv[kh * 3 + kw] = xp[kh * XP + kw];
            #pragma unroll
            for (int r = 0; r < RN; r++) {
                const float* wp = &swB[(r * CIN + ic) * 9];
                #pragma unroll
                for (int t = 0; t < 9; t++) lg[r] = fmaf(wp[t], xv[t], lg[r]);
            }
        }
        if (half == 1) {
            #pragma unroll
            for (int r = 0; r < RN; r++) spart[r * 128 + px] = lg[r];
        }
        __syncthreads();
        if (half == 0) {
            #pragma unroll
            for (int r = 0; r < RN; r++) lg[r] += spart[r * 128 + px] + maskb[r];
            float mx = fmaxf(fmaxf(lg[0], lg[1]), fmaxf(lg[2], lg[3]));
            float e[RN]; float s = 0.f;
            #pragma unroll
            for (int r = 0; r < RN; r++) { e[r] = expf(lg[r] - mx); s += e[r]; }
            float inv = 1.f / s;
            #pragma unroll
            for (int r = 0; r < RN; r++) {
                float m = e[r] * inv;
                sm[r * (TH * TW) + px] = m;
                out[MASK_BASE + ((size_t)(b * RN + r) * HH + (h0 + row)) * WW + (w0 + col)] = m;
            }
        }
        __syncthreads();
    }

    // ---------------- phase 2: dynamic conv, region-folded, double-buffered W ----------------
    // Thread computes 8 oc (as 4 f32x2 pairs) x 4 px (along w).
    const int ocg8 = (tid >> 5) << 3;        // warp-uniform -> broadcast W reads
    const int pxg  = tid & 31;
    const int prow = pxg >> 3;               // 0..3
    const int pcol = (pxg & 7) << 2;         // 0,4,...,28

    u64 accF[4][4];
    const u64 Z = pk2(0.f, 0.f);
    #pragma unroll
    for (int j = 0; j < 4; j++)
        #pragma unroll
        for (int p = 0; p < 4; p++) accF[j][p] = Z;

    int stage = 0;
    for (int r = 0; r < RN; r++) {
        u64 accR[4][4];
        #pragma unroll
        for (int j = 0; j < 4; j++)
            #pragma unroll
            for (int p = 0; p < 4; p++) accR[j][p] = Z;

        for (int c = 0; c < CIN / ICB; c++, stage++) {
            float* cur = (stage & 1) ? swB : swA;
            float* nxt = (stage & 1) ? swA : swB;

            cpa_wait0();          // this stage's W has landed (locally)
            __syncthreads();      // ...and is visible; prior stage's readers done with nxt
            if (stage + 1 < NSTAGE) prefetch_w(kbase, stage + 1, nxt, tid);

            const int ic0 = c * ICB;
            #pragma unroll 2
            for (int i = 0; i < ICB; i++) {
                const float* xrow = &sx[((ic0 + i) * XROWS + prow) * XP + pcol];
                #pragma unroll
                for (int kh = 0; kh < 3; kh++) {
                    const float* xp = xrow + kh * XP;
                    float4 xa = *(const float4*)xp;         // cols pcol..pcol+3
                    float4 xc = *(const float4*)(xp + 4);   // cols pcol+4..pcol+7 (z,w unused)
                    u64 xx[6];
                    xx[0] = pk2(xa.x, xa.x); xx[1] = pk2(xa.y, xa.y);
                    xx[2] = pk2(xa.z, xa.z); xx[3] = pk2(xa.w, xa.w);
                    xx[4] = pk2(xc.x, xc.x); xx[5] = pk2(xc.y, xc.y);
                    const float* wrow = &cur[(i * 9 + kh * 3) * WPITCH + ocg8];
                    #pragma unroll
                    for (int kw = 0; kw < 3; kw++) {
                        const ulonglong2* wp = (const ulonglong2*)(wrow + kw * WPITCH);
                        ulonglong2 Wa = wp[0];   // oc pairs (0,1),(2,3)
                        ulonglong2 Wb = wp[1];   // oc pairs (4,5),(6,7)
                        #pragma unroll
                        for (int p = 0; p < 4; p++) {
                            u64 xv2 = xx[kw + p];
                            accR[0][p] = f2ma(Wa.x, xv2, accR[0][p]);
                            accR[1][p] = f2ma(Wa.y, xv2, accR[1][p]);
                            accR[2][p] = f2ma(Wb.x, xv2, accR[2][p]);
                            accR[3][p] = f2ma(Wb.y, xv2, accR[3][p]);
                        }
                    }
                }
            }
        }
        // fold this region with its mask weight
        #pragma unroll
        for (int p = 0; p < 4; p++) {
            float m = sm[r * (TH * TW) + prow * TW + pcol + p];
            u64 mm = pk2(m, m);
            #pragma unroll
            for (int j = 0; j < 4; j++) accF[j][p] = f2ma(mm, accR[j][p], accF[j][p]);
        }
    }

    // ---------------- epilogue: BN (eval) + ReLU, float4 stores ----------------
    const size_t obase = (size_t)b * COUT * HH * WW;
    const int gh  = h0 + prow;
    const int gwc = w0 + pcol;
    #pragma unroll
    for (int j = 0; j < 4; j++) {
        int oc0 = ocg8 + 2 * j;
        float i0 = bn_g[oc0]     / sqrtf(bn_v[oc0]     + 1e-5f);
        float i1 = bn_g[oc0 + 1] / sqrtf(bn_v[oc0 + 1] + 1e-5f);
        float m0 = bn_m[oc0], m1 = bn_m[oc0 + 1];
        float c0 = bn_b[oc0], c1 = bn_b[oc0 + 1];
        float v0[4], v1[4];
        #pragma unroll
        for (int p = 0; p < 4; p++) {
            float a0, a1; up2(accF[j][p], a0, a1);
            v0[p] = fmaxf((a0 - m0) * i0 + c0, 0.f);
            v1[p] = fmaxf((a1 - m1) * i1 + c1, 0.f);
        }
        *(float4*)&out[obase + ((size_t)oc0 * HH + gh) * WW + gwc] =
            make_float4(v0[0], v0[1], v0[2], v0[3]);
        *(float4*)&out[obase + ((size_t)(oc0 + 1) * HH + gh) * WW + gwc] =
            make_float4(v1[0], v1[1], v1[2], v1[3]);
    }
}

extern "C" void kernel_launch(void* const* d_in, const int* in_sizes, int n_in,
                              void* d_out, int out_size)
{
    const float* x  = (const float*)d_in[0];
    const float* k  = (const float*)d_in[1];
    const float* mw = (const float*)d_in[2];
    const float* mb = (const float*)d_in[3];
    const float* g  = (const float*)d_in[4];
    const float* be = (const float*)d_in[5];
    const float* mn = (const float*)d_in[6];
    const float* vr = (const float*)d_in[7];

    cudaFuncSetAttribute(hrc_kernel, cudaFuncAttributeMaxDynamicSharedMemorySize, SMEM_BYTES);

    dim3 grid(WW / TW, HH / TH, BB);   // 4 x 32 x 8 = 1024 blocks
    hrc_kernel<<<grid, NTHR, SMEM_BYTES>>>(x, k, mw, mb, g, be, mn, vr, (float*)d_out);
}